// round 6
// baseline (speedup 1.0000x reference)
#include <cuda_runtime.h>
#include <cstdint>

// out[n,64] = sum over edges e with dst[e]==n of x[src[e],:] * w[e]
// Inputs: x (float32, N*64), edge_index ((2,E), int64-or-int32), edge_weight (float32, E)

static constexpr int D       = 64;   // feature dim
static constexpr int TPB     = 256;  // threads per block
static constexpr int BATCH   = 256;  // edges staged per block
static constexpr int GROUPS  = TPB / 16;       // 16 edge-groups per pass
static constexpr int PASSES  = BATCH / GROUPS; // 16 serial edges per thread
static constexpr int UNROLL  = 8;    // gathers in flight per thread (full path)

// Probe result: 1 if edge_index is stored as int64, 0 if int32.
__device__ int g_idx_is64;

// Fused: zero the output AND (block 0 only) probe the index dtype.
// int64 indices < 2^31 => every odd 32-bit word is zero; int32 indices are
// random node ids, so all-zero over 1024 samples has probability ~1e-5024.
__global__ void zero_and_probe_kernel(float4* __restrict__ out, int n4,
                                      const int* __restrict__ ei32, int E) {
    if (blockIdx.x == 0) {
        __shared__ int any_nonzero;
        if (threadIdx.x == 0) any_nonzero = 0;
        __syncthreads();
        int n = E < 1024 ? E : 1024;
        for (int i = threadIdx.x; i < n; i += blockDim.x)
            if (ei32[2 * i + 1] != 0) any_nonzero = 1;
        __syncthreads();
        if (threadIdx.x == 0) g_idx_is64 = (any_nonzero == 0) ? 1 : 0;
    }
    int i = blockIdx.x * blockDim.x + threadIdx.x;
    if (i < n4) out[i] = make_float4(0.f, 0.f, 0.f, 0.f);
}

__device__ __forceinline__ void red_v4(float* p, float4 m) {
    asm volatile("red.global.add.v4.f32 [%0], {%1, %2, %3, %4};"
                 :: "l"(p), "f"(m.x), "f"(m.y), "f"(m.z), "f"(m.w)
                 : "memory");
}

__global__ __launch_bounds__(TPB)
void mp_scatter_batched_kernel(const float* __restrict__ x,
                               const void* __restrict__ edge_index,
                               const float* __restrict__ w,
                               float* __restrict__ out,
                               int E) {
    __shared__ int   s_src[BATCH];
    __shared__ int   s_dst[BATCH];
    __shared__ float s_w[BATCH];

    const int t     = threadIdx.x;
    const int lane  = t & 15;   // which float4 of the 64-dim row
    const int group = t >> 4;   // which edge within a pass

    const int base = blockIdx.x * BATCH;
    const int n = (E - base < BATCH) ? (E - base) : BATCH;

    // ---- Stage batch of edges into smem (coalesced; int64 -> int32) ----
    if (t < n) {
        if (g_idx_is64) {
            const long long* p = (const long long*)edge_index;
            s_src[t] = (int)__ldg(p + base + t);
            s_dst[t] = (int)__ldg(p + E + base + t);
        } else {
            const int* p = (const int*)edge_index;
            s_src[t] = __ldg(p + base + t);
            s_dst[t] = __ldg(p + E + base + t);
        }
        s_w[t] = __ldg(w + base + t);
    }
    __syncthreads();

    if (n == BATCH) {
        // ---- Fast path: full batch, branch-free, 8 gathers in flight ----
        #pragma unroll
        for (int p = 0; p < PASSES; p += UNROLL) {
            int    dsts[UNROLL];
            float  wts [UNROLL];
            float4 xv  [UNROLL];

            #pragma unroll
            for (int u = 0; u < UNROLL; u++) {
                int i = group + GROUPS * (p + u);
                unsigned s = (unsigned)s_src[i];
                dsts[u] = s_dst[i];
                wts [u] = s_w[i];
                xv[u] = __ldg(reinterpret_cast<const float4*>(x + s * D) + lane);
            }
            #pragma unroll
            for (int u = 0; u < UNROLL; u++) {
                float wt = wts[u];
                float4 m;
                m.x = xv[u].x * wt; m.y = xv[u].y * wt;
                m.z = xv[u].z * wt; m.w = xv[u].w * wt;
                red_v4(out + (unsigned)dsts[u] * D + lane * 4, m);
            }
        }
    } else {
        // ---- Tail path: guarded (at most one block) ----
        for (int p = 0; p < PASSES; p += 4) {
            int    eidx[4];
            int    dsts[4];
            float  wts [4];
            float4 xv  [4];
            #pragma unroll
            for (int u = 0; u < 4; u++) {
                int i = group + GROUPS * (p + u);
                eidx[u] = i;
                bool ok = (i < n);
                unsigned s = ok ? (unsigned)s_src[i] : 0u;
                dsts[u] = ok ? s_dst[i] : 0;
                wts [u] = ok ? s_w[i]   : 0.f;
                xv[u] = __ldg(reinterpret_cast<const float4*>(x + s * D) + lane);
            }
            #pragma unroll
            for (int u = 0; u < 4; u++) {
                if (eidx[u] < n) {
                    float wt = wts[u];
                    float4 m;
                    m.x = xv[u].x * wt; m.y = xv[u].y * wt;
                    m.z = xv[u].z * wt; m.w = xv[u].w * wt;
                    red_v4(out + (unsigned)dsts[u] * D + lane * 4, m);
                }
            }
        }
    }
}

extern "C" void kernel_launch(void* const* d_in, const int* in_sizes, int n_in,
                              void* d_out, int out_size) {
    const float* x   = (const float*)d_in[0];
    const void*  ei  = d_in[1];
    const float* w   = (const float*)d_in[2];
    float*       out = (float*)d_out;

    const int E = in_sizes[1] / 2;   // edge_index is (2, E)

    // 1) zero output (poisoned 0xAA) + probe index dtype (block 0)
    {
        int n4 = out_size / 4;
        int blocks = (n4 + TPB - 1) / TPB;
        zero_and_probe_kernel<<<blocks, TPB>>>((float4*)out, n4,
                                               (const int*)ei, E);
    }

    // 2) batched gather-multiply-scatter
    {
        int blocks = (E + BATCH - 1) / BATCH;
        mp_scatter_batched_kernel<<<blocks, TPB>>>(x, ei, w, out, E);
    }
}